// round 12
// baseline (speedup 1.0000x reference)
#include <cuda_runtime.h>
#include <math.h>

#define PS 32
#define NB 36
#define NBH 37                 // 0..36; bin 36 = obig==36 edge, folded into bin 0
#define WPB 8
#define THREADS (WPB * 32)
#define NCOPY 32               // one private hist copy per lane

typedef unsigned long long u64p;

__device__ __forceinline__ u64p pk(float lo, float hi) {
    u64p r; asm("mov.b64 %0, {%1, %2};" : "=l"(r) : "f"(lo), "f"(hi)); return r;
}
__device__ __forceinline__ void upk(u64p v, float& lo, float& hi) {
    asm("mov.b64 {%0, %1}, %2;" : "=f"(lo), "=f"(hi) : "l"(v));
}
__device__ __forceinline__ u64p add2(u64p a, u64p b) {
    u64p r; asm("add.rn.f32x2 %0, %1, %2;" : "=l"(r) : "l"(a), "l"(b)); return r;
}
__device__ __forceinline__ u64p mul2(u64p a, u64p b) {
    u64p r; asm("mul.rn.f32x2 %0, %1, %2;" : "=l"(r) : "l"(a), "l"(b)); return r;
}
__device__ __forceinline__ u64p fma2(u64p a, u64p b, u64p c) {
    u64p r; asm("fma.rn.f32x2 %0, %1, %2, %3;" : "=l"(r) : "l"(a), "l"(b), "l"(c)); return r;
}

#define PKC(v) ((((u64p)__float_as_uint(v)) << 32) | (u64p)__float_as_uint(v))

__global__ __launch_bounds__(THREADS, 6)
void orient_kernel(const float* __restrict__ x,
                   const float* __restrict__ gk,
                   float* __restrict__ out,
                   int B, float c_hi, float c_lo)
{
    __shared__ __align__(8) float s_priv[WPB][NBH * NCOPY];

    const int tid   = threadIdx.x;
    const int w     = tid >> 5;
    const int lane  = tid & 31;
    const int patch = blockIdx.x * WPB + w;
    const bool valid = (patch < B);

    float* priv = s_priv[w];
    {   // packed zeroing: NBH*NCOPY floats = 592 u64 per warp
        u64p* pz = (u64p*)priv;
        for (int i = lane; i < (NBH * NCOPY) / 2; i += 32) pz[i] = 0ull;
    }
    __syncwarp();

    const float PI_F  = 3.14159265358979323846f;
    const float TPI_F = 6.28318530717958647692f;
    const unsigned FULL = 0xffffffffu;

    const u64p NEG12 = PKC(-1.0f);
    const u64p PI2   = PKC(PI_F);
    const u64p C362  = PKC(36.0f);
    const u64p EPS42 = PKC(4e-10f);
    const u64p HALF2 = PKC(0.5f);
    const u64p NEGH2 = PKC(-0.5f);
    const u64p CHI2  = PKC(c_hi);
    const u64p CLO2  = PKC(c_lo);

    const int h    = lane >> 4;              // row-half
    const int hl   = lane & 15;              // column-pair index
    const int col0 = 2 * hl;
    const int rlim = h ? 15 : 16;            // clamp for tail prefetch

    const float* xp = x + (size_t)(valid ? patch : 0) * (PS * PS);
    const float* xh = xp + h * 16 * PS;
    const float* gkh = gk + h * 16 * PS + col0;

    float2 cur = *(const float2*)(xh + col0);
    float2 prv = (h == 0) ? cur : *(const float2*)(xh - PS + col0);
    float2 nxt = *(const float2*)(xh + PS + col0);

    #pragma unroll
    for (int r = 0; r < 16; r++) {
        float Lup = __shfl_up_sync(FULL, cur.y, 1, 16);
        float Rdn = __shfl_down_sync(FULL, cur.x, 1, 16);
        float left0  = (hl == 0)  ? cur.x : Lup;
        float right1 = (hl == 15) ? cur.y : Rdn;

        // Unscaled gradients (atan2f bit-invariant to exact 0.5 scaling)
        u64p prv2 = pk(prv.x, prv.y);
        u64p nxt2 = pk(nxt.x, nxt.y);
        u64p dy2  = fma2(nxt2, NEG12, prv2);              // prv - nxt
        u64p ga   = pk(left0, cur.x);
        u64p gb   = pk(cur.y, right1);
        u64p dx2  = fma2(gb, NEG12, ga);                  // left - right

        float dx0, dx1, dy0, dy1;
        upk(dx2, dx0, dx1);
        upk(dy2, dy0, dy1);

        // FROZEN: libdevice atan2f (bit-exact vs XLA)
        float ori0 = atan2f(dy0, dx0);
        float ori1 = atan2f(dy1, dx1);

        // FROZEN chain: t36 = RN(36*RN(ori+pi)); obig = RN(t36/TPI_F) via
        // correctly-rounded double-float multiply
        u64p t36   = mul2(add2(pk(ori0, ori1), PI2), C362);
        u64p obig2 = fma2(t36, CHI2, mul2(t36, CLO2));
        float obig0, obig1; upk(obig2, obig0, obig1);
        float bo00 = floorf(obig0);
        float bo01 = floorf(obig1);
        int bx = (int)bo00;                  // 0..36, no wrap (37-bin hist)
        int by = (int)bo01;

        // continuous path: mag = sqrt(dx^2+dy^2+4e-10) * gk ; reference's 0.5
        // grad scale folded into the (0.5 - 0.5*wo1) weight.
        u64p wo2  = fma2(pk(bo00, bo01), NEG12, obig2);
        u64p m2v  = fma2(dx2, dx2, fma2(dy2, dy2, EPS42));
        float m20, m21; upk(m2v, m20, m21);
        u64p rs2  = pk(rsqrtf(m20), rsqrtf(m21));
        float2 gkv = __ldg((const float2*)(gkh + r * PS));
        u64p mag2 = mul2(mul2(m2v, rs2), pk(gkv.x, gkv.y));
        u64p wv2  = mul2(fma2(wo2, NEGH2, HALF2), mag2);   // (1-wo1)*0.5*mag
        float wx, wy; upk(wv2, wx, wy);

        // per-lane private hist: bank == lane, no conflicts, no races
        priv[bx * NCOPY + lane] += wx;
        priv[by * NCOPY + lane] += wy;

        prv = cur;
        cur = nxt;
        if (r < 15) {
            int nr = r + 2;                   // compile-time except clamp at r=14
            if (nr > rlim) nr = rlim;         // h=1: reload row 31 == replicate
            nxt = *(const float2*)(xh + nr * PS + col0);
        }
    }
    __syncwarp();

    // fold bin 36 (obig==36.0 edge) into bin 0: packed, conflict-free
    if (lane < 16) {
        u64p* p0  = (u64p*)priv;
        u64p* p36 = (u64p*)(priv + 36 * NCOPY);
        p0[lane] = add2(p0[lane], p36[lane]);
    }
    __syncwarp();

    // reduce 32 copies -> 36 bins with packed LDS.64 (rotated, 2-way max)
    u64p acc1 = 0ull;
    #pragma unroll
    for (int c = 0; c < 16; c++) {
        int cc0 = 2 * ((c + lane) & 15);
        acc1 = add2(acc1, *(const u64p*)(priv + lane * NCOPY + cc0));
    }
    float a1lo, a1hi; upk(acc1, a1lo, a1hi);
    float s1 = a1lo + a1hi;

    const int l2 = 32 + (lane & 3);
    u64p acc2 = 0ull;
    #pragma unroll
    for (int c = 0; c < 16; c++) {
        int cc0 = 2 * ((c + lane) & 15);
        acc2 = add2(acc2, *(const u64p*)(priv + l2 * NCOPY + cc0));
    }
    float a2lo, a2hi; upk(acc2, a2lo, a2hi);
    float s2 = a2lo + a2hi;
    __syncwarp();                      // all reduction reads of priv done

    // reuse priv: hist at priv[0..35], smoothed at priv[64..99]
    priv[lane] = s1;
    if (lane < 4) priv[32 + lane] = s2;
    __syncwarp();

    {
        float h0 = priv[lane];
        float hm = (lane > 0) ? priv[lane - 1] : 0.0f;
        float hp = priv[lane + 1];
        float a  = __fmul_rn(0.33f, hm);
        float bb = __fmul_rn(0.34f, h0);
        float c  = __fmul_rn(0.33f, hp);
        priv[64 + lane] = __fadd_rn(__fadd_rn(a, bb), c);
    }
    if (lane < 4) {
        int i = 32 + lane;
        float h0 = priv[i];
        float hm = priv[i - 1];
        float hp = (i < NB - 1) ? priv[i + 1] : 0.0f;
        float a  = __fmul_rn(0.33f, hm);
        float bb = __fmul_rn(0.34f, h0);
        float c  = __fmul_rn(0.33f, hp);
        priv[64 + i] = __fadd_rn(__fadd_rn(a, bb), c);
    }
    __syncwarp();

    if (lane == 0 && valid) {
        float best = priv[64];
        int   bi   = 0;
        #pragma unroll
        for (int i = 1; i < NB; i++) {
            float v = priv[64 + i];
            if (v > best) { best = v; bi = i; }
        }
        float ang = __fsub_rn(__fdiv_rn(__fmul_rn(TPI_F, (float)bi), (float)NB), PI_F);
        out[patch] = -ang;
    }
}

extern "C" void kernel_launch(void* const* d_in, const int* in_sizes, int n_in,
                              void* d_out, int out_size)
{
    const float* x  = (const float*)d_in[0];
    const float* gk = (const float*)d_in[1];
    float* out = (float*)d_out;
    int B = in_sizes[0] / (PS * PS);
    int nblocks = (B + WPB - 1) / WPB;

    const float TPI_F = 6.28318530717958647692f;
    double inv = 1.0 / (double)TPI_F;
    float c_hi = (float)inv;
    float c_lo = (float)(inv - (double)c_hi);

    orient_kernel<<<nblocks, THREADS>>>(x, gk, out, B, c_hi, c_lo);
}

// round 13
// speedup vs baseline: 1.0616x; 1.0616x over previous
#include <cuda_runtime.h>
#include <math.h>

#define PS 32
#define NB 36
#define NBH 37                 // 0..36; bin 36 = obig==36 edge, folded into bin 0
#define WPB 8
#define THREADS (WPB * 32)
#define NCOPY 32               // one private hist copy per lane

typedef unsigned long long u64p;

__device__ __forceinline__ u64p pk(float lo, float hi) {
    u64p r; asm("mov.b64 %0, {%1, %2};" : "=l"(r) : "f"(lo), "f"(hi)); return r;
}
__device__ __forceinline__ void upk(u64p v, float& lo, float& hi) {
    asm("mov.b64 {%0, %1}, %2;" : "=f"(lo), "=f"(hi) : "l"(v));
}
__device__ __forceinline__ u64p add2(u64p a, u64p b) {
    u64p r; asm("add.rn.f32x2 %0, %1, %2;" : "=l"(r) : "l"(a), "l"(b)); return r;
}
__device__ __forceinline__ u64p mul2(u64p a, u64p b) {
    u64p r; asm("mul.rn.f32x2 %0, %1, %2;" : "=l"(r) : "l"(a), "l"(b)); return r;
}
__device__ __forceinline__ u64p fma2(u64p a, u64p b, u64p c) {
    u64p r; asm("fma.rn.f32x2 %0, %1, %2, %3;" : "=l"(r) : "l"(a), "l"(b), "l"(c)); return r;
}

#define PKC(v) ((((u64p)__float_as_uint(v)) << 32) | (u64p)__float_as_uint(v))

__global__ __launch_bounds__(THREADS, 6)
void orient_kernel(const float* __restrict__ x,
                   const float* __restrict__ gk,
                   float* __restrict__ out,
                   int B, float c_hi, float c_lo)
{
    __shared__ __align__(8) float s_priv[WPB][NBH * NCOPY];

    const int tid   = threadIdx.x;
    const int w     = tid >> 5;
    const int lane  = tid & 31;
    const int patch = blockIdx.x * WPB + w;
    const bool valid = (patch < B);

    float* priv = s_priv[w];
    {   // packed zeroing: NBH*NCOPY floats = 592 u64 per warp (FULLY UNROLLED)
        u64p* pz = (u64p*)priv;
        #pragma unroll
        for (int i = lane; i < (NBH * NCOPY) / 2; i += 32) pz[i] = 0ull;
    }
    __syncwarp();

    const float PI_F  = 3.14159265358979323846f;
    const float TPI_F = 6.28318530717958647692f;
    const unsigned FULL = 0xffffffffu;

    const u64p NEG12 = PKC(-1.0f);
    const u64p PI2   = PKC(PI_F);
    const u64p C362  = PKC(36.0f);
    const u64p EPS42 = PKC(4e-10f);
    const u64p HALF2 = PKC(0.5f);
    const u64p NEGH2 = PKC(-0.5f);
    const u64p CHI2  = PKC(c_hi);
    const u64p CLO2  = PKC(c_lo);

    const int h    = lane >> 4;              // row-half
    const int hl   = lane & 15;              // column-pair index
    const int col0 = 2 * hl;
    const int rlim = h ? 15 : 16;            // clamp for tail prefetch

    const float* xp = x + (size_t)(valid ? patch : 0) * (PS * PS);
    const float* xh = xp + h * 16 * PS;
    const float* gkh = gk + h * 16 * PS + col0;

    float2 cur = *(const float2*)(xh + col0);
    float2 prv = (h == 0) ? cur : *(const float2*)(xh - PS + col0);
    float2 nxt = *(const float2*)(xh + PS + col0);

    #pragma unroll
    for (int r = 0; r < 16; r++) {
        float Lup = __shfl_up_sync(FULL, cur.y, 1, 16);
        float Rdn = __shfl_down_sync(FULL, cur.x, 1, 16);
        float left0  = (hl == 0)  ? cur.x : Lup;
        float right1 = (hl == 15) ? cur.y : Rdn;

        // Unscaled gradients (atan2f bit-invariant to exact 0.5 scaling)
        u64p prv2 = pk(prv.x, prv.y);
        u64p nxt2 = pk(nxt.x, nxt.y);
        u64p dy2  = fma2(nxt2, NEG12, prv2);              // prv - nxt
        u64p ga   = pk(left0, cur.x);
        u64p gb   = pk(cur.y, right1);
        u64p dx2  = fma2(gb, NEG12, ga);                  // left - right

        float dx0, dx1, dy0, dy1;
        upk(dx2, dx0, dx1);
        upk(dy2, dy0, dy1);

        // FROZEN: libdevice atan2f (bit-exact vs XLA)
        float ori0 = atan2f(dy0, dx0);
        float ori1 = atan2f(dy1, dx1);

        // FROZEN chain: t36 = RN(36*RN(ori+pi)); obig = RN(t36/TPI_F) via
        // correctly-rounded double-float multiply
        u64p t36   = mul2(add2(pk(ori0, ori1), PI2), C362);
        u64p obig2 = fma2(t36, CHI2, mul2(t36, CLO2));
        float obig0, obig1; upk(obig2, obig0, obig1);
        float bo00 = floorf(obig0);
        float bo01 = floorf(obig1);
        int bx = (int)bo00;                  // 0..36, no wrap (37-bin hist)
        int by = (int)bo01;

        // continuous path: mag = sqrt(dx^2+dy^2+4e-10) * gk ; reference's 0.5
        // grad scale folded into the (0.5 - 0.5*wo1) weight.
        u64p wo2  = fma2(pk(bo00, bo01), NEG12, obig2);
        u64p m2v  = fma2(dx2, dx2, fma2(dy2, dy2, EPS42));
        float m20, m21; upk(m2v, m20, m21);
        u64p rs2  = pk(rsqrtf(m20), rsqrtf(m21));
        float2 gkv = __ldg((const float2*)(gkh + r * PS));
        u64p mag2 = mul2(mul2(m2v, rs2), pk(gkv.x, gkv.y));
        u64p wv2  = mul2(fma2(wo2, NEGH2, HALF2), mag2);   // (1-wo1)*0.5*mag
        float wx, wy; upk(wv2, wx, wy);

        // per-lane private hist: bank == lane, no conflicts, no races
        priv[bx * NCOPY + lane] += wx;
        priv[by * NCOPY + lane] += wy;

        prv = cur;
        cur = nxt;
        if (r < 15) {
            int nr = r + 2;
            if (nr > rlim) nr = rlim;         // h=1: reload row 31 == replicate
            nxt = *(const float2*)(xh + nr * PS + col0);
        }
    }
    __syncwarp();

    // fold bin 36 (obig==36.0 edge) into bin 0: packed, conflict-free
    if (lane < 16) {
        u64p* p0  = (u64p*)priv;
        u64p* p36 = (u64p*)(priv + 36 * NCOPY);
        p0[lane] = add2(p0[lane], p36[lane]);
    }
    __syncwarp();

    // reduce 32 copies -> 36 bins with packed LDS.64 (rotated, 2-way max)
    u64p acc1 = 0ull;
    #pragma unroll
    for (int c = 0; c < 16; c++) {
        int cc0 = 2 * ((c + lane) & 15);
        acc1 = add2(acc1, *(const u64p*)(priv + lane * NCOPY + cc0));
    }
    float a1lo, a1hi; upk(acc1, a1lo, a1hi);
    float s1 = a1lo + a1hi;

    const int l2 = 32 + (lane & 3);
    u64p acc2 = 0ull;
    #pragma unroll
    for (int c = 0; c < 16; c++) {
        int cc0 = 2 * ((c + lane) & 15);
        acc2 = add2(acc2, *(const u64p*)(priv + l2 * NCOPY + cc0));
    }
    float a2lo, a2hi; upk(acc2, a2lo, a2hi);
    float s2 = a2lo + a2hi;
    __syncwarp();                      // all reduction reads of priv done

    // hist staged at priv[0..35]
    priv[lane] = s1;
    if (lane < 4) priv[32 + lane] = s2;
    __syncwarp();

    // smoothing (zero-padded [0.33,0.34,0.33]) straight into registers
    float sv;                                   // smoothed bin = lane
    {
        float h0 = priv[lane];                  // == s1
        float hm = (lane > 0) ? priv[lane - 1] : 0.0f;
        float hp = priv[lane + 1];              // lane 31 -> priv[32] valid
        float a  = __fmul_rn(0.33f, hm);
        float bb = __fmul_rn(0.34f, h0);
        float c  = __fmul_rn(0.33f, hp);
        sv = __fadd_rn(__fadd_rn(a, bb), c);
    }
    float sv2 = __int_as_float(0xff800000);     // -inf
    if (lane < 4) {                             // smoothed bins 32..35
        int i  = 32 + lane;
        float h0 = priv[i];
        float hm = priv[i - 1];
        float hp = (i < NB - 1) ? priv[i + 1] : 0.0f;
        float a  = __fmul_rn(0.33f, hm);
        float bb = __fmul_rn(0.34f, h0);
        float c  = __fmul_rn(0.33f, hp);
        sv2 = __fadd_rn(__fadd_rn(a, bb), c);
    }

    // first-occurrence argmax via butterfly (tie -> lower index, like jnp.argmax)
    float bv = sv;
    int   bi = lane;
    if (sv2 > bv) { bv = sv2; bi = 32 + lane; } // idx 32+lane > lane: strict >
    #pragma unroll
    for (int off = 16; off > 0; off >>= 1) {
        float ov = __shfl_xor_sync(FULL, bv, off);
        int   oi = __shfl_xor_sync(FULL, bi, off);
        if (ov > bv || (ov == bv && oi < bi)) { bv = ov; bi = oi; }
    }

    if (lane == 0 && valid) {
        float ang = __fsub_rn(__fdiv_rn(__fmul_rn(TPI_F, (float)bi), (float)NB), PI_F);
        out[patch] = -ang;
    }
}

extern "C" void kernel_launch(void* const* d_in, const int* in_sizes, int n_in,
                              void* d_out, int out_size)
{
    const float* x  = (const float*)d_in[0];
    const float* gk = (const float*)d_in[1];
    float* out = (float*)d_out;
    int B = in_sizes[0] / (PS * PS);
    int nblocks = (B + WPB - 1) / WPB;

    const float TPI_F = 6.28318530717958647692f;
    double inv = 1.0 / (double)TPI_F;
    float c_hi = (float)inv;
    float c_lo = (float)(inv - (double)c_hi);

    orient_kernel<<<nblocks, THREADS>>>(x, gk, out, B, c_hi, c_lo);
}

// round 14
// speedup vs baseline: 1.0923x; 1.0289x over previous
#include <cuda_runtime.h>
#include <math.h>

#define PS 32
#define NB 36
#define NBH 37                 // 0..36; bin 36 = obig==36 edge, folded into bin 0
#define WPB 8
#define THREADS (WPB * 32)
#define NCOPY 32               // one private hist copy per lane

typedef unsigned long long u64p;

__device__ __forceinline__ u64p pk(float lo, float hi) {
    u64p r; asm("mov.b64 %0, {%1, %2};" : "=l"(r) : "f"(lo), "f"(hi)); return r;
}
__device__ __forceinline__ void upk(u64p v, float& lo, float& hi) {
    asm("mov.b64 {%0, %1}, %2;" : "=f"(lo), "=f"(hi) : "l"(v));
}
__device__ __forceinline__ u64p add2(u64p a, u64p b) {
    u64p r; asm("add.rn.f32x2 %0, %1, %2;" : "=l"(r) : "l"(a), "l"(b)); return r;
}
__device__ __forceinline__ u64p mul2(u64p a, u64p b) {
    u64p r; asm("mul.rn.f32x2 %0, %1, %2;" : "=l"(r) : "l"(a), "l"(b)); return r;
}
__device__ __forceinline__ u64p fma2(u64p a, u64p b, u64p c) {
    u64p r; asm("fma.rn.f32x2 %0, %1, %2, %3;" : "=l"(r) : "l"(a), "l"(b), "l"(c)); return r;
}

#define PKC(v) ((((u64p)__float_as_uint(v)) << 32) | (u64p)__float_as_uint(v))

__global__ __launch_bounds__(THREADS, 6)
void orient_kernel(const float* __restrict__ x,
                   const float* __restrict__ gk,
                   float* __restrict__ out,
                   int B, float c_hi, float c_lo)
{
    __shared__ __align__(8) float s_priv[WPB][NBH * NCOPY];

    const int tid   = threadIdx.x;
    const int w     = tid >> 5;
    const int lane  = tid & 31;
    const int patch = blockIdx.x * WPB + w;
    const bool valid = (patch < B);

    float* priv = s_priv[w];
    {   // packed zeroing (fully unrolled)
        u64p* pz = (u64p*)priv;
        #pragma unroll
        for (int i = lane; i < (NBH * NCOPY) / 2; i += 32) pz[i] = 0ull;
    }
    __syncwarp();

    const float PI_F  = 3.14159265358979323846f;
    const float TPI_F = 6.28318530717958647692f;
    const unsigned FULL = 0xffffffffu;

    const u64p NEG12 = PKC(-1.0f);
    const u64p PI2   = PKC(PI_F);
    const u64p C362  = PKC(36.0f);
    const u64p EPS42 = PKC(4e-10f);
    const u64p HALF2 = PKC(0.5f);
    const u64p NEGH2 = PKC(-0.5f);
    const u64p CHI2  = PKC(c_hi);
    const u64p CLO2  = PKC(c_lo);

    const int h    = lane >> 4;              // row-half
    const int hl   = lane & 15;              // column-pair index
    const int col0 = 2 * hl;
    const int rlim = h ? 15 : 16;            // clamp for tail prefetch

    const float* xp = x + (size_t)(valid ? patch : 0) * (PS * PS);
    const float* xh = xp + h * 16 * PS;
    const float* gkh = gk + h * 16 * PS + col0;

    float2 cur = *(const float2*)(xh + col0);
    float2 prv = (h == 0) ? cur : *(const float2*)(xh - PS + col0);
    float2 nxt = *(const float2*)(xh + PS + col0);

    #pragma unroll
    for (int r = 0; r < 16; r++) {
        float Lup = __shfl_up_sync(FULL, cur.y, 1, 16);
        float Rdn = __shfl_down_sync(FULL, cur.x, 1, 16);
        float left0  = (hl == 0)  ? cur.x : Lup;
        float right1 = (hl == 15) ? cur.y : Rdn;

        // Unscaled gradients (atan2f bit-invariant to exact 0.5 scaling)
        u64p prv2 = pk(prv.x, prv.y);
        u64p nxt2 = pk(nxt.x, nxt.y);
        u64p dy2  = fma2(nxt2, NEG12, prv2);              // prv - nxt
        u64p ga   = pk(left0, cur.x);
        u64p gb   = pk(cur.y, right1);
        u64p dx2  = fma2(gb, NEG12, ga);                  // left - right

        float dx0, dx1, dy0, dy1;
        upk(dx2, dx0, dx1);
        upk(dy2, dy0, dy1);

        // FROZEN: libdevice atan2f (bit-exact vs XLA)
        float ori0 = atan2f(dy0, dx0);
        float ori1 = atan2f(dy1, dx1);

        // FROZEN chain: t36 = RN(36*RN(ori+pi)); obig = RN(t36/TPI_F) via
        // correctly-rounded double-float multiply
        u64p t36   = mul2(add2(pk(ori0, ori1), PI2), C362);
        u64p obig2 = fma2(t36, CHI2, mul2(t36, CLO2));
        float obig0, obig1; upk(obig2, obig0, obig1);
        float bo00 = floorf(obig0);
        float bo01 = floorf(obig1);
        int bx = (int)bo00;                  // 0..36, no wrap (37-bin hist)
        int by = (int)bo01;

        // continuous path: mag = sqrt(dx^2+dy^2+4e-10) * gk ; reference's 0.5
        // grad scale folded into the (0.5 - 0.5*wo1) weight.
        u64p wo2  = fma2(pk(bo00, bo01), NEG12, obig2);
        u64p m2v  = fma2(dx2, dx2, fma2(dy2, dy2, EPS42));
        float m20, m21; upk(m2v, m20, m21);
        u64p rs2  = pk(rsqrtf(m20), rsqrtf(m21));
        float2 gkv = __ldg((const float2*)(gkh + r * PS));
        u64p mag2 = mul2(mul2(m2v, rs2), pk(gkv.x, gkv.y));
        u64p wv2  = mul2(fma2(wo2, NEGH2, HALF2), mag2);   // (1-wo1)*0.5*mag
        float wx, wy; upk(wv2, wx, wy);

        // per-lane private hist: bank == lane, no conflicts, no races
        priv[bx * NCOPY + lane] += wx;
        priv[by * NCOPY + lane] += wy;

        prv = cur;
        cur = nxt;
        if (r < 15) {
            int nr = r + 2;
            if (nr > rlim) nr = rlim;         // h=1: reload row 31 == replicate
            nxt = *(const float2*)(xh + nr * PS + col0);
        }
    }
    __syncwarp();

    // fold bin 36 (obig==36.0 edge) into bin 0: packed, conflict-free
    if (lane < 16) {
        u64p* p0  = (u64p*)priv;
        u64p* p36 = (u64p*)(priv + 36 * NCOPY);
        p0[lane] = add2(p0[lane], p36[lane]);
    }
    __syncwarp();

    // pass 1: bins 0..31 (bin = lane), packed LDS.64, rotated (2-way max)
    u64p acc1 = 0ull;
    #pragma unroll
    for (int c = 0; c < 16; c++) {
        int cc0 = 2 * ((c + lane) & 15);
        acc1 = add2(acc1, *(const u64p*)(priv + lane * NCOPY + cc0));
    }
    float a1lo, a1hi; upk(acc1, a1lo, a1hi);
    float s1 = a1lo + a1hi;

    // pass 2 (distributed): bins 32..35, 8 lanes per bin, 2 u64 per lane,
    // then width-8 butterfly sum. Lane l holds total of bin 32+(l>>3).
    float p2;
    {
        const int bb = 32 + (lane >> 3);
        const u64p* pb = (const u64p*)(priv + bb * NCOPY);
        int k = (lane & 7) * 2;
        u64p a = add2(pb[k], pb[k + 1]);
        float alo, ahi; upk(a, alo, ahi);
        p2 = alo + ahi;
        p2 += __shfl_xor_sync(FULL, p2, 1);
        p2 += __shfl_xor_sync(FULL, p2, 2);
        p2 += __shfl_xor_sync(FULL, p2, 4);
    }

    // smoothing via shuffles (no smem staging). Exact ops as before.
    float v32 = __shfl_sync(FULL, p2, 0);            // bin 32 total
    float hm  = __shfl_up_sync(FULL, s1, 1);
    float hp  = __shfl_down_sync(FULL, s1, 1);
    if (lane == 0)  hm = 0.0f;
    if (lane == 31) hp = v32;
    float sv;
    {
        float a  = __fmul_rn(0.33f, hm);
        float bb = __fmul_rn(0.34f, s1);
        float c  = __fmul_rn(0.33f, hp);
        sv = __fadd_rn(__fadd_rn(a, bb), c);
    }

    // high bins 32..35 smoothed on lanes 0..3
    float h0h, hmh, hph;
    {
        int i8  = (lane < 4) ? lane * 8 : 0;
        h0h = __shfl_sync(FULL, p2, i8);             // bin 32+lane (lanes 0-3)
        float hm31 = __shfl_sync(FULL, s1, 31);      // bin 31
        int im8 = (lane >= 1 && lane < 4) ? (lane - 1) * 8 : 0;
        hmh = __shfl_sync(FULL, p2, im8);            // bin 31+lane for lanes 1-3
        if (lane == 0) hmh = hm31;
        int ip8 = (lane < 3) ? (lane + 1) * 8 : 0;
        hph = __shfl_sync(FULL, p2, ip8);            // bin 33+lane for lanes 0-2
        if (lane >= 3) hph = 0.0f;                   // bin 35: zero pad
    }
    float sv2 = __int_as_float(0xff800000);          // -inf
    if (lane < 4) {
        float a  = __fmul_rn(0.33f, hmh);
        float bb = __fmul_rn(0.34f, h0h);
        float c  = __fmul_rn(0.33f, hph);
        sv2 = __fadd_rn(__fadd_rn(a, bb), c);
    }

    // first-occurrence argmax via butterfly (tie -> lower index)
    float bv = sv;
    int   bi = lane;
    if (sv2 > bv) { bv = sv2; bi = 32 + lane; }
    #pragma unroll
    for (int off = 16; off > 0; off >>= 1) {
        float ov = __shfl_xor_sync(FULL, bv, off);
        int   oi = __shfl_xor_sync(FULL, bi, off);
        if (ov > bv || (ov == bv && oi < bi)) { bv = ov; bi = oi; }
    }

    if (lane == 0 && valid) {
        float ang = __fsub_rn(__fdiv_rn(__fmul_rn(TPI_F, (float)bi), (float)NB), PI_F);
        out[patch] = -ang;
    }
}

extern "C" void kernel_launch(void* const* d_in, const int* in_sizes, int n_in,
                              void* d_out, int out_size)
{
    const float* x  = (const float*)d_in[0];
    const float* gk = (const float*)d_in[1];
    float* out = (float*)d_out;
    int B = in_sizes[0] / (PS * PS);
    int nblocks = (B + WPB - 1) / WPB;

    const float TPI_F = 6.28318530717958647692f;
    double inv = 1.0 / (double)TPI_F;
    float c_hi = (float)inv;
    float c_lo = (float)(inv - (double)c_hi);

    orient_kernel<<<nblocks, THREADS>>>(x, gk, out, B, c_hi, c_lo);
}

// round 16
// speedup vs baseline: 1.1214x; 1.0267x over previous
#include <cuda_runtime.h>
#include <math.h>

#define PS 32
#define NB 36
#define NBH 37                 // 0..36; bin 36 = obig==36 edge, folded into bin 0
#define WPB 8
#define THREADS (WPB * 32)
#define NCOPY 32               // one private hist copy per lane

typedef unsigned long long u64p;

__device__ __forceinline__ u64p pk(float lo, float hi) {
    u64p r; asm("mov.b64 %0, {%1, %2};" : "=l"(r) : "f"(lo), "f"(hi)); return r;
}
__device__ __forceinline__ void upk(u64p v, float& lo, float& hi) {
    asm("mov.b64 {%0, %1}, %2;" : "=f"(lo), "=f"(hi) : "l"(v));
}
__device__ __forceinline__ u64p add2(u64p a, u64p b) {
    u64p r; asm("add.rn.f32x2 %0, %1, %2;" : "=l"(r) : "l"(a), "l"(b)); return r;
}
__device__ __forceinline__ u64p mul2(u64p a, u64p b) {
    u64p r; asm("mul.rn.f32x2 %0, %1, %2;" : "=l"(r) : "l"(a), "l"(b)); return r;
}
__device__ __forceinline__ u64p fma2(u64p a, u64p b, u64p c) {
    u64p r; asm("fma.rn.f32x2 %0, %1, %2, %3;" : "=l"(r) : "l"(a), "l"(b), "l"(c)); return r;
}

#define PKC(v) ((((u64p)__float_as_uint(v)) << 32) | (u64p)__float_as_uint(v))

__global__ __launch_bounds__(THREADS, 6)
void orient_kernel(const float* __restrict__ x,
                   const float* __restrict__ gk,
                   float* __restrict__ out,
                   int B, float c_hi, float c_lo)
{
    __shared__ __align__(16) float s_priv[WPB][NBH * NCOPY];

    const int tid   = threadIdx.x;
    const int w     = tid >> 5;
    const int lane  = tid & 31;
    const int patch = blockIdx.x * WPB + w;
    const bool valid = (patch < B);

    float* priv = s_priv[w];
    {   // packed zeroing (fully unrolled)
        u64p* pz = (u64p*)priv;
        #pragma unroll
        for (int i = lane; i < (NBH * NCOPY) / 2; i += 32) pz[i] = 0ull;
    }
    __syncwarp();

    const float PI_F  = 3.14159265358979323846f;
    const float TPI_F = 6.28318530717958647692f;
    const unsigned FULL = 0xffffffffu;

    const u64p NEG12 = PKC(-1.0f);
    const u64p PI2   = PKC(PI_F);
    const u64p C362  = PKC(36.0f);
    const u64p EPS42 = PKC(4e-10f);
    const u64p HALF2 = PKC(0.5f);
    const u64p NEGH2 = PKC(-0.5f);
    const u64p CHI2  = PKC(c_hi);
    const u64p CLO2  = PKC(c_lo);

    const int h    = lane >> 4;              // row-half
    const int hl   = lane & 15;              // column-pair index
    const int col0 = 2 * hl;

    const float* xp = x + (size_t)(valid ? patch : 0) * (PS * PS);
    const float* xh = xp + h * 16 * PS;
    const float* gkh = gk + h * 16 * PS + col0;
    // tail row pointer: h=0 -> row 16 (real), h=1 -> row 31 (replicate)
    const float* xtail = xh + (h ? 15 : 16) * PS + col0;

    float2 cur = *(const float2*)(xh + col0);
    float2 prv = (h == 0) ? cur : *(const float2*)(xh - PS + col0);
    float2 nxt = *(const float2*)(xh + PS + col0);

    #pragma unroll
    for (int r = 0; r < 16; r++) {
        float Lup = __shfl_up_sync(FULL, cur.y, 1, 16);
        float Rdn = __shfl_down_sync(FULL, cur.x, 1, 16);
        float left0  = (hl == 0)  ? cur.x : Lup;
        float right1 = (hl == 15) ? cur.y : Rdn;

        // Unscaled gradients (atan2f bit-invariant to exact 0.5 scaling)
        u64p prv2 = pk(prv.x, prv.y);
        u64p nxt2 = pk(nxt.x, nxt.y);
        u64p dy2  = fma2(nxt2, NEG12, prv2);              // prv - nxt
        u64p ga   = pk(left0, cur.x);
        u64p gb   = pk(cur.y, right1);
        u64p dx2  = fma2(gb, NEG12, ga);                  // left - right

        float dx0, dx1, dy0, dy1;
        upk(dx2, dx0, dx1);
        upk(dy2, dy0, dy1);

        // FROZEN: libdevice atan2f (bit-exact vs XLA)
        float ori0 = atan2f(dy0, dx0);
        float ori1 = atan2f(dy1, dx1);

        // FROZEN chain: t36 = RN(36*RN(ori+pi)); obig = RN(t36/TPI_F) via
        // correctly-rounded double-float multiply
        u64p t36   = mul2(add2(pk(ori0, ori1), PI2), C362);
        u64p obig2 = fma2(t36, CHI2, mul2(t36, CLO2));
        float obig0, obig1; upk(obig2, obig0, obig1);
        float bo00 = floorf(obig0);
        float bo01 = floorf(obig1);
        int bx = (int)bo00;                  // 0..36, no wrap (37-bin hist)
        int by = (int)bo01;

        // continuous path: mag = sqrt(dx^2+dy^2+4e-10) * gk ; reference's 0.5
        // grad scale folded into the (0.5 - 0.5*wo1) weight.
        u64p wo2  = fma2(pk(bo00, bo01), NEG12, obig2);
        u64p m2v  = fma2(dx2, dx2, fma2(dy2, dy2, EPS42));
        float m20, m21; upk(m2v, m20, m21);
        u64p rs2  = pk(rsqrtf(m20), rsqrtf(m21));
        float2 gkv = __ldg((const float2*)(gkh + r * PS));
        u64p mag2 = mul2(mul2(m2v, rs2), pk(gkv.x, gkv.y));
        u64p wv2  = mul2(fma2(wo2, NEGH2, HALF2), mag2);   // (1-wo1)*0.5*mag
        float wx, wy; upk(wv2, wx, wy);

        // per-lane private hist: bank == lane, no conflicts, no races
        priv[bx * NCOPY + lane] += wx;
        priv[by * NCOPY + lane] += wy;

        prv = cur;
        cur = nxt;
        // compile-time immediate offsets for r<14; clamp ONLY the r=14 load
        if (r < 14)       nxt = *(const float2*)(xh + (r + 2) * PS + col0);
        else if (r == 14) nxt = *(const float2*)xtail;
    }
    __syncwarp();

    // fold bin 36 (obig==36.0 edge) into bin 0: packed, conflict-free
    if (lane < 16) {
        u64p* p0  = (u64p*)priv;
        u64p* p36 = (u64p*)(priv + 36 * NCOPY);
        p0[lane] = add2(p0[lane], p36[lane]);
    }
    __syncwarp();

    // pass 1: bins 0..31 (bin = lane), LDS.128, rotated (even/odd-copy
    // partition preserved; intra-partition order reassociated)
    u64p acc1 = 0ull;
    {
        const float* row = priv + lane * NCOPY;
        #pragma unroll
        for (int c = 0; c < 8; c++) {
            int cc = 4 * ((c + lane) & 7);
            float4 v = *(const float4*)(row + cc);
            acc1 = add2(acc1, pk(v.x, v.y));
            acc1 = add2(acc1, pk(v.z, v.w));
        }
    }
    float a1lo, a1hi; upk(acc1, a1lo, a1hi);
    float s1 = a1lo + a1hi;

    // pass 2 (distributed): bins 32..35, 8 lanes per bin, one LDS.128 each,
    // then width-8 butterfly sum. Lane l holds total of bin 32+(l>>3).
    float p2;
    {
        const int bb = 32 + (lane >> 3);
        const float* pb = priv + bb * NCOPY + (lane & 7) * 4;
        float4 v = *(const float4*)pb;
        u64p a = add2(pk(v.x, v.y), pk(v.z, v.w));
        float alo, ahi; upk(a, alo, ahi);
        p2 = alo + ahi;
        p2 += __shfl_xor_sync(FULL, p2, 1);
        p2 += __shfl_xor_sync(FULL, p2, 2);
        p2 += __shfl_xor_sync(FULL, p2, 4);
    }

    // smoothing via shuffles (no smem staging)
    float v32 = __shfl_sync(FULL, p2, 0);            // bin 32 total
    float hm  = __shfl_up_sync(FULL, s1, 1);
    float hp  = __shfl_down_sync(FULL, s1, 1);
    if (lane == 0)  hm = 0.0f;
    if (lane == 31) hp = v32;
    float sv;
    {
        float a  = __fmul_rn(0.33f, hm);
        float bb = __fmul_rn(0.34f, s1);
        float c  = __fmul_rn(0.33f, hp);
        sv = __fadd_rn(__fadd_rn(a, bb), c);
    }

    // high bins 32..35 smoothed on lanes 0..3
    float h0h, hmh, hph;
    {
        int i8  = (lane < 4) ? lane * 8 : 0;
        h0h = __shfl_sync(FULL, p2, i8);             // bin 32+lane (lanes 0-3)
        float hm31 = __shfl_sync(FULL, s1, 31);      // bin 31
        int im8 = (lane >= 1 && lane < 4) ? (lane - 1) * 8 : 0;
        hmh = __shfl_sync(FULL, p2, im8);            // bin 31+lane for lanes 1-3
        if (lane == 0) hmh = hm31;
        int ip8 = (lane < 3) ? (lane + 1) * 8 : 0;
        hph = __shfl_sync(FULL, p2, ip8);            // bin 33+lane for lanes 0-2
        if (lane >= 3) hph = 0.0f;                   // bin 35: zero pad
    }
    float sv2 = __int_as_float(0xff800000);          // -inf
    if (lane < 4) {
        float a  = __fmul_rn(0.33f, hmh);
        float bb = __fmul_rn(0.34f, h0h);
        float c  = __fmul_rn(0.33f, hph);
        sv2 = __fadd_rn(__fadd_rn(a, bb), c);
    }

    // first-occurrence argmax via butterfly (tie -> lower index)
    float bv = sv;
    int   bi = lane;
    if (sv2 > bv) { bv = sv2; bi = 32 + lane; }
    #pragma unroll
    for (int off = 16; off > 0; off >>= 1) {
        float ov = __shfl_xor_sync(FULL, bv, off);
        int   oi = __shfl_xor_sync(FULL, bi, off);
        if (ov > bv || (ov == bv && oi < bi)) { bv = ov; bi = oi; }
    }

    if (lane == 0 && valid) {
        float ang = __fsub_rn(__fdiv_rn(__fmul_rn(TPI_F, (float)bi), (float)NB), PI_F);
        out[patch] = -ang;
    }
}

extern "C" void kernel_launch(void* const* d_in, const int* in_sizes, int n_in,
                              void* d_out, int out_size)
{
    const float* x  = (const float*)d_in[0];
    const float* gk = (const float*)d_in[1];
    float* out = (float*)d_out;
    int B = in_sizes[0] / (PS * PS);
    int nblocks = (B + WPB - 1) / WPB;

    const float TPI_F = 6.28318530717958647692f;
    double inv = 1.0 / (double)TPI_F;
    float c_hi = (float)inv;
    float c_lo = (float)(inv - (double)c_hi);

    orient_kernel<<<nblocks, THREADS>>>(x, gk, out, B, c_hi, c_lo);
}